// round 1
// baseline (speedup 1.0000x reference)
#include <cuda_runtime.h>
#include <math.h>

// Problem constants (shapes fixed by the dataset)
#define NMAX 100000
#define INC 64
#define HIDC 128
#define OUTC 64

// Scratch (device globals — no allocation allowed)
__device__ __align__(256) float g_agg1[NMAX * INC];    // 25.6 MB
__device__ __align__(256) float g_h[NMAX * HIDC];      // 51.2 MB
__device__ __align__(256) float g_agg2[NMAX * HIDC];   // 51.2 MB
__device__ __align__(256) float g_deg[NMAX];

// ---------------------------------------------------------------------------
// k_zero: clear agg1, agg2, deg
// ---------------------------------------------------------------------------
__global__ void k_zero(int n) {
    long t1 = (long)n * INC;
    long t2 = t1 + (long)n * HIDC;
    long total = t2 + n;
    for (long i = (long)blockIdx.x * blockDim.x + threadIdx.x; i < total;
         i += (long)gridDim.x * blockDim.x) {
        if (i < t1)       g_agg1[i] = 0.f;
        else if (i < t2)  g_agg2[i - t1] = 0.f;
        else              g_deg[i - t2] = 0.f;
    }
}

// ---------------------------------------------------------------------------
// Vector reduction-add helper (sm_90+): one L2 atomic per 16B
// ---------------------------------------------------------------------------
__device__ __forceinline__ void red_add_v4(float* addr, float4 v) {
    asm volatile("red.global.add.v4.f32 [%0], {%1,%2,%3,%4};"
                 :: "l"(addr), "f"(v.x), "f"(v.y), "f"(v.z), "f"(v.w)
                 : "memory");
}

// ---------------------------------------------------------------------------
// k_scatter1: agg1[dst] += x[src]  (64 ch -> 16 threads/edge, float4 each)
//             also deg[dst] += 1
// ---------------------------------------------------------------------------
__global__ void __launch_bounds__(256) k_scatter1(
    const float4* __restrict__ x4, const int* __restrict__ src,
    const int* __restrict__ dst, int E) {
    long idx = (long)blockIdx.x * blockDim.x + threadIdx.x;
    long total = (long)E * 16;
    if (idx >= total) return;
    int e = (int)(idx >> 4);
    int p = (int)(idx & 15);
    int s = src[e];
    int d = dst[e];
    float4 v = x4[(long)s * 16 + p];
    red_add_v4(g_agg1 + (long)d * INC + p * 4, v);
    if (p == 0) atomicAdd(g_deg + d, 1.0f);
}

// ---------------------------------------------------------------------------
// k_scatter2: agg2[dst] += h[src]  (128 ch -> 32 threads/edge, float4 each)
// ---------------------------------------------------------------------------
__global__ void __launch_bounds__(256) k_scatter2(
    const int* __restrict__ src, const int* __restrict__ dst, int E) {
    long idx = (long)blockIdx.x * blockDim.x + threadIdx.x;
    long total = (long)E * 32;
    if (idx >= total) return;
    int e = (int)(idx >> 5);
    int p = (int)(idx & 31);
    int s = src[e];
    int d = dst[e];
    const float4* h4 = (const float4*)g_h;
    float4 v = h4[(long)s * 32 + p];
    red_add_v4(g_agg2 + (long)d * HIDC + p * 4, v);
}

// ---------------------------------------------------------------------------
// k_dense1: h = relu( (agg1/deg) @ W1_l^T + b1 + x @ W1_r^T )
//   blockDim = 128 (= HID_C). Weights in smem transposed as w[c][o]
//   (lane-consecutive o -> conflict-free LDS). One node per iteration.
// ---------------------------------------------------------------------------
__global__ void __launch_bounds__(128) k_dense1(
    const float* __restrict__ x, const float* __restrict__ W1l,
    const float* __restrict__ W1r, const float* __restrict__ b1, int n) {
    extern __shared__ float smem[];
    float* wl = smem;              // [64][128]
    float* wr = smem + INC * HIDC; // [64][128]
    __shared__ float xs[INC];
    __shared__ float as_[INC];
    __shared__ float bsh[HIDC];
    __shared__ float inv;

    int tid = threadIdx.x;
    // Load weights transposed: wl[c*128+o] = W1l[o*64+c]
    for (int i = tid; i < HIDC * INC; i += 128) {
        int o = i >> 6, c = i & 63;
        wl[c * HIDC + o] = W1l[i];
        wr[c * HIDC + o] = W1r[i];
    }
    bsh[tid] = b1[tid];
    __syncthreads();

    for (int node = blockIdx.x; node < n; node += gridDim.x) {
        if (tid < 64)        xs[tid] = x[(long)node * INC + tid];
        else                 as_[tid - 64] = g_agg1[(long)node * INC + tid - 64];
        if (tid == 0)        inv = 1.0f / fmaxf(g_deg[node], 1.0f);
        __syncthreads();

        float acc = bsh[tid];
        float accA = 0.f;
        #pragma unroll
        for (int c = 0; c < INC; c++) {
            accA = fmaf(as_[c], wl[c * HIDC + tid], accA);
            acc  = fmaf(xs[c],  wr[c * HIDC + tid], acc);
        }
        float v = fmaf(accA, inv, acc);
        g_h[(long)node * HIDC + tid] = fmaxf(v, 0.f);
        __syncthreads();
    }
}

// ---------------------------------------------------------------------------
// k_dense2: out = sigmoid( (agg2/deg) @ W2_l^T + b2 + h @ W2_r^T )
//   blockDim = 128: o = tid&63, two nodes per iteration (half = tid>>6).
// ---------------------------------------------------------------------------
__global__ void __launch_bounds__(128) k_dense2(
    const float* __restrict__ W2l, const float* __restrict__ W2r,
    const float* __restrict__ b2, float* __restrict__ out, int n) {
    extern __shared__ float smem[];
    float* wl = smem;               // [128][64]
    float* wr = smem + HIDC * OUTC; // [128][64]
    __shared__ float hs[2 * HIDC];
    __shared__ float as2[2 * HIDC];
    __shared__ float bsh[OUTC];
    __shared__ float inv2[2];

    int tid = threadIdx.x;
    int o = tid & 63;
    int half = tid >> 6;

    // Load weights transposed: wl[c*64+o] = W2l[o*128+c]
    for (int i = tid; i < OUTC * HIDC; i += 128) {
        int oo = i >> 7, c = i & 127;
        wl[c * OUTC + oo] = W2l[i];
        wr[c * OUTC + oo] = W2r[i];
    }
    if (tid < OUTC) bsh[tid] = b2[tid];
    __syncthreads();

    for (int base = blockIdx.x * 2; base < n; base += gridDim.x * 2) {
        // stage two nodes' h and agg2 rows (each thread loads 2+2 values)
        #pragma unroll
        for (int t = 0; t < 2; t++) {
            if (base + t < n) {
                hs[t * HIDC + tid]  = g_h[(long)(base + t) * HIDC + tid];
                as2[t * HIDC + tid] = g_agg2[(long)(base + t) * HIDC + tid];
            }
        }
        if (tid < 2 && base + tid < n)
            inv2[tid] = 1.0f / fmaxf(g_deg[base + tid], 1.0f);
        __syncthreads();

        int node = base + half;
        if (node < n) {
            float acc = bsh[o];
            float accA = 0.f;
            #pragma unroll
            for (int c = 0; c < HIDC; c++) {
                accA = fmaf(as2[half * HIDC + c], wl[c * OUTC + o], accA);
                acc  = fmaf(hs[half * HIDC + c],  wr[c * OUTC + o], acc);
            }
            float v = fmaf(accA, inv2[half], acc);
            out[(long)node * OUTC + o] = 1.0f / (1.0f + __expf(-v));
        }
        __syncthreads();
    }
}

// ---------------------------------------------------------------------------
// kernel_launch
// Inputs (metadata order): x, edge_index, W1_l, W1_r, b1, W2_l, W2_r, b2
// ---------------------------------------------------------------------------
extern "C" void kernel_launch(void* const* d_in, const int* in_sizes, int n_in,
                              void* d_out, int out_size) {
    const float* x    = (const float*)d_in[0];
    const int*   ei   = (const int*)d_in[1];
    const float* W1l  = (const float*)d_in[2];
    const float* W1r  = (const float*)d_in[3];
    const float* b1   = (const float*)d_in[4];
    const float* W2l  = (const float*)d_in[5];
    const float* W2r  = (const float*)d_in[6];
    const float* b2   = (const float*)d_in[7];
    float* out = (float*)d_out;

    int n = in_sizes[0] / INC;
    int E = in_sizes[1] / 2;
    const int* src = ei;
    const int* dst = ei + E;

    static bool attr_done = false;
    // cudaFuncSetAttribute is host-side state, not a stream op; set every call
    // is also fine but do it once cheaply (idempotent, not a work guard).
    if (!attr_done) {
        cudaFuncSetAttribute(k_dense1, cudaFuncAttributeMaxDynamicSharedMemorySize, 2 * INC * HIDC * 4);
        cudaFuncSetAttribute(k_dense2, cudaFuncAttributeMaxDynamicSharedMemorySize, 2 * HIDC * OUTC * 4);
        attr_done = true;
    }

    // k0: zero scratch
    {
        long total = (long)n * (INC + HIDC) + n;
        int blocks = (int)((total + 255) / 256);
        if (blocks > 65535 * 4) blocks = 65535 * 4;
        k_zero<<<blocks, 256>>>(n);
    }
    // k1: layer1 scatter (+deg)
    {
        long total = (long)E * 16;
        int blocks = (int)((total + 255) / 256);
        k_scatter1<<<blocks, 256>>>((const float4*)x, src, dst, E);
    }
    // k2: layer1 dense -> h
    k_dense1<<<444, 128, 2 * INC * HIDC * 4>>>(x, W1l, W1r, b1, n);
    // k3: layer2 scatter
    {
        long total = (long)E * 32;
        int blocks = (int)((total + 255) / 256);
        k_scatter2<<<blocks, 256>>>(src, dst, E);
    }
    // k4: layer2 dense -> out
    k_dense2<<<444, 128, 2 * HIDC * OUTC * 4>>>(W2l, W2r, b2, out, n);
}

// round 3
// speedup vs baseline: 2.1247x; 2.1247x over previous
#include <cuda_runtime.h>
#include <math.h>

#define NMAX 100000
#define INC 64
#define HIDC 128
#define OUTC 64

typedef unsigned long long ull;

// Scratch (device globals — no allocation allowed)
__device__ __align__(256) float g_agg1[NMAX * INC];    // 25.6 MB
__device__ __align__(256) float g_h[NMAX * HIDC];      // 51.2 MB
__device__ __align__(256) float g_z[NMAX * OUTC];      // 25.6 MB  z = h @ W2l^T
__device__ __align__(256) float g_zagg[NMAX * OUTC];   // 25.6 MB  scattered z
__device__ __align__(256) float g_deg[NMAX];
// Transposed weights (filled by k_prep each call)
__device__ __align__(256) float g_Wcat[HIDC * HIDC];   // [k][o]: k<64->W1l, k>=64->W1r
__device__ __align__(256) float g_W2lT[HIDC * OUTC];   // [k][o]
__device__ __align__(256) float g_W2rT[HIDC * OUTC];   // [k][o]

// ---------------- packed f32x2 helpers ----------------
__device__ __forceinline__ void fma2(ull& d, ull a, ull b) {
    asm("fma.rn.f32x2 %0, %1, %2, %0;" : "+l"(d) : "l"(a), "l"(b));
}
__device__ __forceinline__ ull pack2(float x) {
    ull r; asm("mov.b64 %0, {%1, %1};" : "=l"(r) : "f"(x)); return r;
}
__device__ __forceinline__ float2 unpack2(ull v) {
    float2 r; asm("mov.b64 {%0, %1}, %2;" : "=f"(r.x), "=f"(r.y) : "l"(v)); return r;
}

// ---------------------------------------------------------------------------
// k_prep: build transposed weight copies (coalesced smem fills for the GEMMs)
// ---------------------------------------------------------------------------
__global__ void k_prep(const float* __restrict__ W1l, const float* __restrict__ W1r,
                       const float* __restrict__ W2l, const float* __restrict__ W2r) {
    int stride = gridDim.x * blockDim.x;
    int tid = blockIdx.x * blockDim.x + threadIdx.x;
    for (int i = tid; i < HIDC * HIDC; i += stride) {
        int k = i >> 7, o = i & 127;
        g_Wcat[i] = (k < 64) ? W1l[o * 64 + k] : W1r[o * 64 + (k - 64)];
    }
    for (int i = tid; i < HIDC * OUTC; i += stride) {
        int k = i >> 6, o = i & 63;
        g_W2lT[i] = W2l[o * 128 + k];
        g_W2rT[i] = W2r[o * 128 + k];
    }
}

// ---------------------------------------------------------------------------
// k_zero: clear agg1, zagg, deg (float4 writes)
// ---------------------------------------------------------------------------
__global__ void k_zero(int n) {
    long t1 = (long)n * (INC / 4);
    long t2 = t1 + (long)n * (OUTC / 4);
    long total = t2 + (n + 3) / 4;
    float4 z = make_float4(0.f, 0.f, 0.f, 0.f);
    for (long i = (long)blockIdx.x * blockDim.x + threadIdx.x; i < total;
         i += (long)gridDim.x * blockDim.x) {
        if (i < t1)       ((float4*)g_agg1)[i] = z;
        else if (i < t2)  ((float4*)g_zagg)[i - t1] = z;
        else              ((float4*)g_deg)[i - t2] = z;
    }
}

// ---------------------------------------------------------------------------
// Vector reduction-add (sm_90+): one L2 atomic per 16B
// ---------------------------------------------------------------------------
__device__ __forceinline__ void red_add_v4(float* addr, float4 v) {
    asm volatile("red.global.add.v4.f32 [%0], {%1,%2,%3,%4};"
                 :: "l"(addr), "f"(v.x), "f"(v.y), "f"(v.z), "f"(v.w)
                 : "memory");
}

// ---------------------------------------------------------------------------
// k_scatter1: agg1[dst] += x[src]  (64 ch -> 16 threads/edge) + deg[dst] += 1
// ---------------------------------------------------------------------------
__global__ void __launch_bounds__(256) k_scatter1(
    const float4* __restrict__ x4, const int* __restrict__ src,
    const int* __restrict__ dst, int E) {
    long idx = (long)blockIdx.x * blockDim.x + threadIdx.x;
    long total = (long)E * 16;
    if (idx >= total) return;
    int e = (int)(idx >> 4);
    int p = (int)(idx & 15);
    int s = src[e];
    int d = dst[e];
    float4 v = x4[(long)s * 16 + p];
    red_add_v4(g_agg1 + (long)d * INC + p * 4, v);
    if (p == 0) atomicAdd(g_deg + d, 1.0f);
}

// ---------------------------------------------------------------------------
// k_scatter2: zagg[dst] += z[src]  (64 ch -> 16 threads/edge)
// ---------------------------------------------------------------------------
__global__ void __launch_bounds__(256) k_scatter2(
    const int* __restrict__ src, const int* __restrict__ dst, int E) {
    long idx = (long)blockIdx.x * blockDim.x + threadIdx.x;
    long total = (long)E * 16;
    if (idx >= total) return;
    int e = (int)(idx >> 4);
    int p = (int)(idx & 15);
    int s = src[e];
    int d = dst[e];
    const float4* z4 = (const float4*)g_z;
    float4 v = z4[(long)s * 16 + p];
    red_add_v4(g_zagg + (long)d * OUTC + p * 4, v);
}

// ---------------------------------------------------------------------------
// k_mlp1: per 64-node tile:
//   a = [inv*agg1 , x]  (K=128)
//   h = relu(a @ Wcat + b1)   -> g_h  (and smem, transposed)
//   z = h @ W2l^T             -> g_z
// Register-tiled GEMM, packed f32x2 FMAs.
// smem: Ws[128][128] (64KB) + W2s[128][64] (32KB) + AH[128][64] (32KB)
// ---------------------------------------------------------------------------
__global__ void __launch_bounds__(256) k_mlp1(
    const float* __restrict__ x, const float* __restrict__ b1, int n) {
    extern __shared__ float sm[];
    float* Ws  = sm;                   // 16384 floats
    float* W2s = sm + 16384;           // 8192 floats
    float* AH  = sm + 16384 + 8192;    // 8192 floats  (A tile, then H tile)
    __shared__ float invs[64];
    __shared__ float b1s[HIDC];

    int tid = threadIdx.x;
    int base = blockIdx.x * 64;

    // fill weight smem (coalesced float4, conflict-free)
    {
        const float4* s4 = (const float4*)g_Wcat;
        float4* d4 = (float4*)Ws;
        for (int i = tid; i < HIDC * HIDC / 4; i += 256) d4[i] = s4[i];
        const float4* s2 = (const float4*)g_W2lT;
        float4* d2 = (float4*)W2s;
        for (int i = tid; i < HIDC * OUTC / 4; i += 256) d2[i] = s2[i];
    }
    if (tid < HIDC) b1s[tid] = b1[tid];
    if (tid < 64) {
        int node = base + tid;
        invs[tid] = (node < n) ? 1.0f / fmaxf(g_deg[node], 1.0f) : 0.f;
    }
    __syncthreads();

    // stage A[k][m]  (k<64: inv*agg1, else x)
    {
        int m = tid >> 2;
        int node = base + m;
        float inv = invs[m];
        int kq = (tid & 3) * 8;
        #pragma unroll
        for (int j = 0; j < 8; j++) {
            int k = (kq + j) * 4;
            float4 v = make_float4(0.f, 0.f, 0.f, 0.f);
            if (node < n) {
                if (k < 64) {
                    v = *(const float4*)(g_agg1 + (long)node * INC + k);
                    v.x *= inv; v.y *= inv; v.z *= inv; v.w *= inv;
                } else {
                    v = *(const float4*)(x + (long)node * INC + (k - 64));
                }
            }
            AH[(k + 0) * 64 + m] = v.x;
            AH[(k + 1) * 64 + m] = v.y;
            AH[(k + 2) * 64 + m] = v.z;
            AH[(k + 3) * 64 + m] = v.w;
        }
    }
    __syncthreads();

    int tx = tid & 15;   // m-group: rows tx*4 .. tx*4+3
    int ty = tid >> 4;   // n-group: cols ty*8 .. ty*8+7 (GEMM1), ty*4.. (zGEMM)

    // ---- GEMM1: h tile 64x128 ----
    ull acc[4][4];
    #pragma unroll
    for (int i = 0; i < 4; i++)
        #pragma unroll
        for (int j = 0; j < 4; j++) acc[i][j] = 0ull;

    #pragma unroll 8
    for (int k = 0; k < HIDC; k++) {
        float4 a = *(float4*)&AH[k * 64 + tx * 4];
        ull av[4];
        av[0] = pack2(a.x); av[1] = pack2(a.y); av[2] = pack2(a.z); av[3] = pack2(a.w);
        ulonglong2 w01 = *(ulonglong2*)&Ws[k * HIDC + ty * 8];
        ulonglong2 w23 = *(ulonglong2*)&Ws[k * HIDC + ty * 8 + 4];
        #pragma unroll
        for (int i = 0; i < 4; i++) {
            fma2(acc[i][0], av[i], w01.x);
            fma2(acc[i][1], av[i], w01.y);
            fma2(acc[i][2], av[i], w23.x);
            fma2(acc[i][3], av[i], w23.y);
        }
    }
    __syncthreads();   // everyone done reading A before we overwrite with H

    // epilogue: bias + relu, write g_h and H[k=o][m] into AH
    #pragma unroll
    for (int i = 0; i < 4; i++) {
        int m = tx * 4 + i;
        int node = base + m;
        float hv[8];
        #pragma unroll
        for (int j = 0; j < 4; j++) {
            float2 p = unpack2(acc[i][j]);
            int o = ty * 8 + j * 2;
            hv[j * 2]     = fmaxf(p.x + b1s[o], 0.f);
            hv[j * 2 + 1] = fmaxf(p.y + b1s[o + 1], 0.f);
        }
        #pragma unroll
        for (int j = 0; j < 8; j++) AH[(ty * 8 + j) * 64 + m] = hv[j];
        if (node < n) {
            *(float4*)(g_h + (long)node * HIDC + ty * 8)     = make_float4(hv[0], hv[1], hv[2], hv[3]);
            *(float4*)(g_h + (long)node * HIDC + ty * 8 + 4) = make_float4(hv[4], hv[5], hv[6], hv[7]);
        }
    }
    __syncthreads();

    // ---- z GEMM: 64x64, z = H @ W2l^T ----
    ull zac[4][2];
    #pragma unroll
    for (int i = 0; i < 4; i++) { zac[i][0] = 0ull; zac[i][1] = 0ull; }

    #pragma unroll 8
    for (int k = 0; k < HIDC; k++) {
        float4 a = *(float4*)&AH[k * 64 + tx * 4];
        ull av[4];
        av[0] = pack2(a.x); av[1] = pack2(a.y); av[2] = pack2(a.z); av[3] = pack2(a.w);
        ulonglong2 w = *(ulonglong2*)&W2s[k * OUTC + ty * 4];
        #pragma unroll
        for (int i = 0; i < 4; i++) {
            fma2(zac[i][0], av[i], w.x);
            fma2(zac[i][1], av[i], w.y);
        }
    }

    #pragma unroll
    for (int i = 0; i < 4; i++) {
        int node = base + tx * 4 + i;
        if (node < n) {
            float2 p0 = unpack2(zac[i][0]);
            float2 p1 = unpack2(zac[i][1]);
            *(float4*)(g_z + (long)node * OUTC + ty * 4) = make_float4(p0.x, p0.y, p1.x, p1.y);
        }
    }
}

// ---------------------------------------------------------------------------
// k_out: out = sigmoid( inv*zagg + b2 + h @ W2r^T )
// smem: Wr[128][64] (32KB) + As[128][64] (32KB)
// ---------------------------------------------------------------------------
__global__ void __launch_bounds__(256) k_out(
    const float* __restrict__ b2, float* __restrict__ out, int n) {
    extern __shared__ float sm[];
    float* Wr = sm;            // 8192 floats
    float* As = sm + 8192;     // 8192 floats
    __shared__ float invs[64];
    __shared__ float b2s[OUTC];

    int tid = threadIdx.x;
    int base = blockIdx.x * 64;

    {
        const float4* s4 = (const float4*)g_W2rT;
        float4* d4 = (float4*)Wr;
        for (int i = tid; i < HIDC * OUTC / 4; i += 256) d4[i] = s4[i];
    }
    if (tid < 64) {
        int node = base + tid;
        invs[tid] = (node < n) ? 1.0f / fmaxf(g_deg[node], 1.0f) : 0.f;
        b2s[tid] = b2[tid];
    }
    __syncthreads();

    // stage h tile transposed As[k][m]
    {
        int m = tid >> 2;
        int node = base + m;
        int kq = (tid & 3) * 8;
        #pragma unroll
        for (int j = 0; j < 8; j++) {
            int k = (kq + j) * 4;
            float4 v = make_float4(0.f, 0.f, 0.f, 0.f);
            if (node < n) v = *(const float4*)(g_h + (long)node * HIDC + k);
            As[(k + 0) * 64 + m] = v.x;
            As[(k + 1) * 64 + m] = v.y;
            As[(k + 2) * 64 + m] = v.z;
            As[(k + 3) * 64 + m] = v.w;
        }
    }
    __syncthreads();

    int tx = tid & 15;
    int ty = tid >> 4;

    ull acc[4][2];
    #pragma unroll
    for (int i = 0; i < 4; i++) { acc[i][0] = 0ull; acc[i][1] = 0ull; }

    #pragma unroll 8
    for (int k = 0; k < HIDC; k++) {
        float4 a = *(float4*)&As[k * 64 + tx * 4];
        ull av[4];
        av[0] = pack2(a.x); av[1] = pack2(a.y); av[2] = pack2(a.z); av[3] = pack2(a.w);
        ulonglong2 w = *(ulonglong2*)&Wr[k * OUTC + ty * 4];
        #pragma unroll
        for (int i = 0; i < 4; i++) {
            fma2(acc[i][0], av[i], w.x);
            fma2(acc[i][1], av[i], w.y);
        }
    }

    #pragma unroll
    for (int i = 0; i < 4; i++) {
        int m = tx * 4 + i;
        int node = base + m;
        if (node < n) {
            float inv = invs[m];
            float4 zg = *(const float4*)(g_zagg + (long)node * OUTC + ty * 4);
            float2 p0 = unpack2(acc[i][0]);
            float2 p1 = unpack2(acc[i][1]);
            int o = ty * 4;
            float v0 = p0.x + b2s[o + 0] + inv * zg.x;
            float v1 = p0.y + b2s[o + 1] + inv * zg.y;
            float v2 = p1.x + b2s[o + 2] + inv * zg.z;
            float v3 = p1.y + b2s[o + 3] + inv * zg.w;
            float4 r;
            r.x = 1.0f / (1.0f + __expf(-v0));
            r.y = 1.0f / (1.0f + __expf(-v1));
            r.z = 1.0f / (1.0f + __expf(-v2));
            r.w = 1.0f / (1.0f + __expf(-v3));
            *(float4*)(out + (long)node * OUTC + o) = r;
        }
    }
}

// ---------------------------------------------------------------------------
// kernel_launch  (inputs: x, edge_index, W1_l, W1_r, b1, W2_l, W2_r, b2)
// ---------------------------------------------------------------------------
extern "C" void kernel_launch(void* const* d_in, const int* in_sizes, int n_in,
                              void* d_out, int out_size) {
    const float* x   = (const float*)d_in[0];
    const int*   ei  = (const int*)d_in[1];
    const float* W1l = (const float*)d_in[2];
    const float* W1r = (const float*)d_in[3];
    const float* b1  = (const float*)d_in[4];
    const float* W2l = (const float*)d_in[5];
    const float* W2r = (const float*)d_in[6];
    const float* b2  = (const float*)d_in[7];
    float* out = (float*)d_out;

    int n = in_sizes[0] / INC;
    int E = in_sizes[1] / 2;
    const int* src = ei;
    const int* dst = ei + E;

    // Idempotent host-side attribute set (not a stream op; capture-safe)
    cudaFuncSetAttribute(k_mlp1, cudaFuncAttributeMaxDynamicSharedMemorySize,
                         (16384 + 8192 + 8192) * 4);
    cudaFuncSetAttribute(k_out, cudaFuncAttributeMaxDynamicSharedMemorySize,
                         (8192 + 8192) * 4);

    int nt = (n + 63) / 64;

    k_prep<<<32, 256>>>(W1l, W1r, W2l, W2r);

    {
        long total = (long)n * 32 + (n + 3) / 4;
        int blocks = (int)((total + 255) / 256);
        k_zero<<<blocks, 256>>>(n);
    }
    {
        long total = (long)E * 16;
        int blocks = (int)((total + 255) / 256);
        k_scatter1<<<blocks, 256>>>((const float4*)x, src, dst, E);
    }
    k_mlp1<<<nt, 256, (16384 + 8192 + 8192) * 4>>>(x, b1, n);
    {
        long total = (long)E * 16;
        int blocks = (int)((total + 255) / 256);
        k_scatter2<<<blocks, 256>>>(src, dst, E);
    }
    k_out<<<nt, 256, (8192 + 8192) * 4>>>(b2, out, n);
}